// round 10
// baseline (speedup 1.0000x reference)
#include <cuda_runtime.h>
#include <cstdint>

// dense_image_warp: out[b,y,x,c] = bilinear(image[b], y - flow[b,y,x,0], x - flow[b,y,x,1])
// B=8, H=512, W=512, C=16, fp32.
// 2 threads per pixel: each owns one 32B half (2 channel groups) of the 64B
// pixel and gathers its 4 bilinear neighbors with LDG.256 (ld.global.nc.v8.f32,
// sm_100+). Halves addr math per channel, doubles outstanding bytes per warp.
// Block = 256 threads = 16(w) x 8(h) pixels x 2 halves; 2 iterations cover a
// 16x16 tile. Flow staged in smem.

#define Hh 512
#define Ww 512

#define LDG256(r, p)                                                        \
    asm volatile("ld.global.nc.v8.f32 {%0,%1,%2,%3,%4,%5,%6,%7}, [%8];"      \
        : "=f"(r[0]), "=f"(r[1]), "=f"(r[2]), "=f"(r[3]),                    \
          "=f"(r[4]), "=f"(r[5]), "=f"(r[6]), "=f"(r[7])                     \
        : "l"(p))

#define STG256(p, r)                                                        \
    asm volatile("st.global.v8.f32 [%0], {%1,%2,%3,%4,%5,%6,%7,%8};"         \
        :: "l"(p),                                                           \
           "f"(r[0]), "f"(r[1]), "f"(r[2]), "f"(r[3]),                       \
           "f"(r[4]), "f"(r[5]), "f"(r[6]), "f"(r[7]) : "memory")

__global__ __launch_bounds__(256) void warp_kernel_v8(
    const float* __restrict__ img,     // [B,H,W,C]
    const float2* __restrict__ flow2,  // flow as float2 per pixel
    float* __restrict__ out)
{
    __shared__ float2 sflow[256];      // 16x16 flow tile

    int t  = threadIdx.x;
    int h  = t & 1;                    // which 32B half of the pixel
    int pi = t >> 1;                   // pixel within sub-tile: 0..127
    int lx = pi & 15;
    int ly = pi >> 4;                  // 0..7

    int x0 = blockIdx.x * 16;
    int y0 = blockIdx.y * 16;
    int b  = blockIdx.z;
    int x  = x0 + lx;

    // ---- stage 16x16 flow tile ----
    {
        int fxp = x0 + (t & 15);
        int fyp = y0 + (t >> 4);
        int fp  = (((b << 9) + fyp) << 9) + fxp;
        sflow[t] = __ldcs(&flow2[fp]);
    }
    __syncthreads();

    #pragma unroll
    for (int it = 0; it < 2; it++) {
        int ty = it * 8 + ly;          // 0..15
        int y  = y0 + ty;

        float2 f = sflow[(ty << 4) + lx];
        float qy = (float)y - f.x;
        float qx = (float)x - f.y;

        float fy = fminf(fmaxf(floorf(qy), 0.0f), (float)(Hh - 2));
        float fx = fminf(fmaxf(floorf(qx), 0.0f), (float)(Ww - 2));
        float ay = fminf(fmaxf(qy - fy, 0.0f), 1.0f);
        float ax = fminf(fmaxf(qx - fx, 0.0f), 1.0f);
        int iy = (int)fy;
        int ix = (int)fx;

        // byte address of TL neighbor's 32B half for this thread
        const char* base = (const char*)img
            + ((size_t)((((b << 9) + iy) << 9) + ix) << 6) + (h << 5);

        float tl[8], tr[8], bl[8], br[8];
        LDG256(tl, base);
        LDG256(tr, base + 64);
        LDG256(bl, base + (Ww << 6));
        LDG256(br, base + (Ww << 6) + 64);

        float r[8];
        #pragma unroll
        for (int c = 0; c < 8; c++) {
            float top = fmaf(ax, tr[c] - tl[c], tl[c]);
            float bot = fmaf(ax, br[c] - bl[c], bl[c]);
            r[c] = fmaf(ay, bot - top, top);
        }

        char* g = (char*)out
            + ((size_t)((((b << 9) + y) << 9) + x) << 6) + (h << 5);
        STG256(g, r);
    }
}

extern "C" void kernel_launch(void* const* d_in, const int* in_sizes, int n_in,
                              void* d_out, int out_size)
{
    const float*  img   = (const float*)d_in[0];
    const float2* flow2 = (const float2*)d_in[1];
    float* out = (float*)d_out;

    dim3 grid(Ww / 16, Hh / 16, 8);
    warp_kernel_v8<<<grid, 256>>>(img, flow2, out);
}